// round 2
// baseline (speedup 1.0000x reference)
#include <cuda_runtime.h>
#include <math.h>

#define B_    4
#define N_    2048
#define F_    16
#define HID_  32
#define H_    6
#define OUT_  16
#define BH_   (B_*H_)
#define CONC_ (H_*HID_)   // 192

// ---------------- scratch (static device allocations are allowed) ----------------
__device__ int   g_cnt[N_];
__device__ int   g_off[N_ + 1];
__device__ int   g_cols[(size_t)N_ * N_];                 // worst-case CSR columns
__device__ float g_h1[(size_t)BH_ * N_ * HID_];           // per (b,h) projected features
__device__ float g_s1[BH_ * N_];
__device__ float g_s2[BH_ * N_];
__device__ float g_x1[(size_t)B_ * N_ * CONC_];           // elu(concat heads)
__device__ float g_h2[B_ * N_ * OUT_];
__device__ float g_t1[B_ * N_];
__device__ float g_t2[B_ * N_];

// ---------------- CSR build ----------------
// adjI = adj + I  =>  edge iff adj[i][j] > 0 || i == j
__global__ void k_count(const float* __restrict__ adj) {
    int row = blockIdx.x * (blockDim.x >> 5) + (threadIdx.x >> 5);
    int lane = threadIdx.x & 31;
    if (row >= N_) return;
    const float* ar = adj + (size_t)row * N_;
    int cnt = 0;
    for (int base = 0; base < N_; base += 32) {
        int j = base + lane;
        cnt += (ar[j] > 0.f || j == row) ? 1 : 0;
    }
    #pragma unroll
    for (int d = 16; d; d >>= 1) cnt += __shfl_xor_sync(0xffffffffu, cnt, d);
    if (lane == 0) g_cnt[row] = cnt;
}

__global__ void k_scan() {
    __shared__ int buf[2][1024];
    int t = threadIdx.x;
    int a = g_cnt[2 * t], b = g_cnt[2 * t + 1];
    int s = a + b;
    buf[0][t] = s;
    __syncthreads();
    int src = 0;
    for (int d = 1; d < 1024; d <<= 1) {
        int v = buf[src][t];
        if (t >= d) v += buf[src][t - d];
        buf[src ^ 1][t] = v;
        src ^= 1;
        __syncthreads();
    }
    int incl = buf[src][t];
    int excl = incl - s;
    g_off[2 * t]     = excl;
    g_off[2 * t + 1] = excl + a;
    if (t == 1023) g_off[2048] = incl;
}

__global__ void k_fill(const float* __restrict__ adj) {
    int row = blockIdx.x * (blockDim.x >> 5) + (threadIdx.x >> 5);
    int lane = threadIdx.x & 31;
    if (row >= N_) return;
    const float* ar = adj + (size_t)row * N_;
    int w = g_off[row];
    for (int base = 0; base < N_; base += 32) {
        int j = base + lane;
        bool pred = (ar[j] > 0.f || j == row);
        unsigned m = __ballot_sync(0xffffffffu, pred);
        if (pred) {
            int pos = w + __popc(m & ((1u << lane) - 1u));
            g_cols[pos] = j;
        }
        w += __popc(m);
    }
}

// ---------------- layer 1 linear: h1 = x @ W1[h], s1/s2 = h1 @ a1 ----------------
// grid (BH_, N_/8), block (32, 8): tx = o, ty = n-in-tile
__global__ void k_l1_linear(const float* __restrict__ x,
                            const float* __restrict__ W1,
                            const float* __restrict__ a1) {
    int bh = blockIdx.x;
    int b = bh / H_, h = bh % H_;
    int o = threadIdx.x;
    int n = blockIdx.y * 8 + threadIdx.y;
    __shared__ float sW[F_ * HID_];   // 16x32 = 512 floats
    __shared__ float sa[2 * HID_];
    int tid = threadIdx.y * 32 + threadIdx.x;
    for (int t = tid; t < F_ * HID_; t += 256) sW[t] = W1[h * F_ * HID_ + t];  // FIX: strided load
    if (tid < 2 * HID_)  sa[tid] = a1[h * 2 * HID_ + tid];
    __syncthreads();
    const float* xr = x + ((size_t)b * N_ + n) * F_;
    float acc = 0.f;
    #pragma unroll
    for (int k = 0; k < F_; k++) acc = fmaf(xr[k], sW[k * HID_ + o], acc);
    g_h1[((size_t)bh * N_ + n) * HID_ + o] = acc;
    float p1 = acc * sa[o];
    float p2 = acc * sa[HID_ + o];
    #pragma unroll
    for (int d = 16; d; d >>= 1) {
        p1 += __shfl_xor_sync(0xffffffffu, p1, d);
        p2 += __shfl_xor_sync(0xffffffffu, p2, d);
    }
    if (o == 0) {
        g_s1[bh * N_ + n] = p1;
        g_s2[bh * N_ + n] = p2;
    }
}

// ---------------- layer 1 sparse attention + ELU-concat ----------------
#define L1WARPS 8
#define CH 128
__global__ void k_l1_attn() {
    int wslot = threadIdx.x >> 5;
    int lane  = threadIdx.x & 31;
    int gw = blockIdx.x * L1WARPS + wslot;              // one warp per (bh, i)
    if (gw >= BH_ * N_) return;
    int i = gw % N_, bh = gw / N_;
    int b = bh / H_, h = bh % H_;
    int off = g_off[i];
    int deg = g_off[i + 1] - off;
    float s1i = g_s1[bh * N_ + i];
    const float* s2r = g_s2 + bh * N_;
    const float* hb  = g_h1 + (size_t)bh * N_ * HID_;

    // pass 1: row max
    float m = -1e30f;
    for (int t = lane; t < deg; t += 32) {
        int j = g_cols[off + t];
        float e = s1i + s2r[j];
        e = e > 0.f ? e : 0.2f * e;
        m = fmaxf(m, e);
    }
    #pragma unroll
    for (int d = 16; d; d >>= 1) m = fmaxf(m, __shfl_xor_sync(0xffffffffu, m, d));

    // pass 2: chunked weights in smem, coalesced feature gather
    __shared__ float sw[L1WARPS][CH];
    __shared__ int   sj[L1WARPS][CH];
    float acc = 0.f, den = 0.f;
    for (int base = 0; base < deg; base += CH) {
        int len = min(CH, deg - base);
        for (int t = lane; t < len; t += 32) {
            int j = g_cols[off + base + t];
            float e = s1i + s2r[j];
            e = e > 0.f ? e : 0.2f * e;
            float w = __expf(e - m);
            den += w;
            sw[wslot][t] = w;
            sj[wslot][t] = j;
        }
        __syncwarp();
        #pragma unroll 4
        for (int t = 0; t < len; t++) {
            acc = fmaf(sw[wslot][t], hb[(size_t)sj[wslot][t] * HID_ + lane], acc);
        }
        __syncwarp();
    }
    #pragma unroll
    for (int d = 16; d; d >>= 1) den += __shfl_xor_sync(0xffffffffu, den, d);
    float v = acc / den;
    v = v > 0.f ? v : expm1f(v);                         // ELU
    g_x1[((size_t)b * N_ + i) * CONC_ + h * HID_ + lane] = v;
}

// ---------------- layer 2 linear: h2 = x1 @ W2, t1/t2 = h2 @ a2 ----------------
// grid (B_, N_/16), block (16,16): tx = o, ty = n-in-tile
__global__ void k_l2_linear(const float* __restrict__ W2,
                            const float* __restrict__ a2) {
    __shared__ float sW[CONC_ * OUT_];                   // 192x16 = 12KB
    __shared__ float sa[2 * OUT_];
    int tid = threadIdx.y * 16 + threadIdx.x;
    for (int t = tid; t < CONC_ * OUT_; t += 256) sW[t] = W2[t];
    if (tid < 2 * OUT_) sa[tid] = a2[tid];
    __syncthreads();
    int b = blockIdx.x;
    int n = blockIdx.y * 16 + threadIdx.y;
    int o = threadIdx.x;
    const float* xr = g_x1 + ((size_t)b * N_ + n) * CONC_;
    float acc = 0.f;
    #pragma unroll
    for (int k = 0; k < CONC_; k++) acc = fmaf(xr[k], sW[k * OUT_ + o], acc);
    g_h2[((size_t)b * N_ + n) * OUT_ + o] = acc;
    float p1 = acc * sa[o];
    float p2 = acc * sa[OUT_ + o];
    #pragma unroll
    for (int d = 8; d; d >>= 1) {
        p1 += __shfl_xor_sync(0xffffffffu, p1, d, 16);
        p2 += __shfl_xor_sync(0xffffffffu, p2, d, 16);
    }
    if (o == 0) {
        g_t1[b * N_ + n] = p1;
        g_t2[b * N_ + n] = p2;
    }
}

// ---------------- layer 2 sparse attention + ELU + final write ----------------
__global__ void k_l2_attn(float* __restrict__ out) {
    int wslot = threadIdx.x >> 5;
    int lane  = threadIdx.x & 31;
    int gw = blockIdx.x * L1WARPS + wslot;               // one warp per (b, i)
    if (gw >= B_ * N_) return;
    int i = gw % N_, b = gw / N_;
    int off = g_off[i];
    int deg = g_off[i + 1] - off;
    float s1i = g_t1[b * N_ + i];
    const float* s2r = g_t2 + b * N_;
    const float* hb  = g_h2 + (size_t)b * N_ * OUT_;

    float m = -1e30f;
    for (int t = lane; t < deg; t += 32) {
        int j = g_cols[off + t];
        float e = s1i + s2r[j];
        e = e > 0.f ? e : 0.2f * e;
        m = fmaxf(m, e);
    }
    #pragma unroll
    for (int d = 16; d; d >>= 1) m = fmaxf(m, __shfl_xor_sync(0xffffffffu, m, d));

    __shared__ float sw[L1WARPS][CH];
    __shared__ int   sj[L1WARPS][CH];
    float acc = 0.f, den = 0.f;
    for (int base = 0; base < deg; base += CH) {
        int len = min(CH, deg - base);
        for (int t = lane; t < len; t += 32) {
            int j = g_cols[off + base + t];
            float e = s1i + s2r[j];
            e = e > 0.f ? e : 0.2f * e;
            float w = __expf(e - m);
            den += w;
            sw[wslot][t] = w;
            sj[wslot][t] = j;
        }
        __syncwarp();
        if (lane < OUT_) {
            #pragma unroll 4
            for (int t = 0; t < len; t++) {
                acc = fmaf(sw[wslot][t], hb[(size_t)sj[wslot][t] * OUT_ + lane], acc);
            }
        }
        __syncwarp();
    }
    #pragma unroll
    for (int d = 16; d; d >>= 1) den += __shfl_xor_sync(0xffffffffu, den, d);
    if (lane < OUT_) {
        float v = acc / den;
        v = v > 0.f ? v : expm1f(v);                     // ELU
        out[((size_t)b * N_ + i) * OUT_ + lane] = v;     // [B,N,1,OUT] contiguous
    }
}

// ---------------- launch ----------------
extern "C" void kernel_launch(void* const* d_in, const int* in_sizes, int n_in,
                              void* d_out, int out_size) {
    const float* flow_x = (const float*)d_in[0];   // [4,2048,16]
    const float* adj    = (const float*)d_in[1];   // [2048,2048]
    const float* W1     = (const float*)d_in[2];   // [6,16,32]
    const float* a1     = (const float*)d_in[3];   // [6,64,1]
    const float* W2     = (const float*)d_in[4];   // [192,16]
    const float* a2     = (const float*)d_in[5];   // [32,1]
    float* out = (float*)d_out;

    // CSR build (shared across batches & heads)
    k_count<<<N_ / 8, 256>>>(adj);
    k_scan<<<1, 1024>>>();
    k_fill<<<N_ / 8, 256>>>(adj);

    // layer 1
    {
        dim3 grid(BH_, N_ / 8);
        dim3 block(32, 8);
        k_l1_linear<<<grid, block>>>(flow_x, W1, a1);
    }
    k_l1_attn<<<(BH_ * N_ + L1WARPS - 1) / L1WARPS, 32 * L1WARPS>>>();

    // layer 2
    {
        dim3 grid(B_, N_ / 16);
        dim3 block(16, 16);
        k_l2_linear<<<grid, block>>>(W2, a2);
    }
    k_l2_attn<<<(B_ * N_ + L1WARPS - 1) / L1WARPS, 32 * L1WARPS>>>(out);
}